// round 14
// baseline (speedup 1.0000x reference)
#include <cuda_runtime.h>
#include <cuda_bf16.h>
#include <math.h>
#include <stdint.h>

typedef unsigned long long u64;
typedef unsigned int u32;

// ---------------- problem constants ----------------
#define NHD   32
#define HD    128
#define BSB   4
#define QL    16
#define CL    4096
#define TTOT  (CL + QL)        // 4112
#define DIMD  4096
#define MROWS 64
#define SZQ   (MROWS * DIMD)   // 262144
#define NS    16               // attention kv splits
#define RANGE 257
#define TT    32               // attention time tile

#define VOFF  ((long)BSB * TTOT * NHD * HD)
#define OOFF  (2l * VOFF)
#define INV_SQRT_HD 0.08838834764831845f

// ---------------- scratch ----------------
__device__ float g_qkv[3l * SZQ];     // xq|xk|xv projections (fp32)
__device__ float g_xq [SZQ];          // roped Q
__device__ float g_attn[SZQ];         // attention out (pre out-proj)
__device__ float g_ao  [(long)BSB * NHD * NS * QL * HD];
__device__ float g_am  [BSB * NHD * NS * QL];
__device__ float g_al  [BSB * NHD * NS * QL];

// ---------------- helpers ----------------
__device__ __forceinline__ u32 smem_u32(const void* p) {
    u32 a;
    asm("{ .reg .u64 t; cvta.to.shared.u64 t, %1; cvt.u32.u64 %0, t; }" : "=r"(a) : "l"(p));
    return a;
}

#define LDMX4(r0, r1, r2, r3, addr) \
    asm volatile("ldmatrix.sync.aligned.m8n8.x4.shared.b16 {%0,%1,%2,%3}, [%4];" \
                 : "=r"(r0), "=r"(r1), "=r"(r2), "=r"(r3) : "r"(addr))

#define LDMX4T(r0, r1, r2, r3, addr) \
    asm volatile("ldmatrix.sync.aligned.m8n8.x4.trans.shared.b16 {%0,%1,%2,%3}, [%4];" \
                 : "=r"(r0), "=r"(r1), "=r"(r2), "=r"(r3) : "r"(addr))

#define LDMX2(r0, r1, addr) \
    asm volatile("ldmatrix.sync.aligned.m8n8.x2.shared.b16 {%0,%1}, [%2];" \
                 : "=r"(r0), "=r"(r1) : "r"(addr))

#define MMA_BF16(d, a, b0, b1) \
    asm volatile("mma.sync.aligned.m16n8k16.row.col.f32.bf16.bf16.f32 " \
                 "{%0,%1,%2,%3}, {%4,%5,%6,%7}, {%8,%9}, {%0,%1,%2,%3};" \
                 : "+f"((d)[0]), "+f"((d)[1]), "+f"((d)[2]), "+f"((d)[3]) \
                 : "r"((a)[0]), "r"((a)[1]), "r"((a)[2]), "r"((a)[3]), "r"(b0), "r"(b1))

// convert float4 -> bf16 hi pair + lo pair, store 8B each.
// hi floats reconstructed from packed bf16 bits (SHL/AND): identical values,
// half the cvt-pipe ops (measured WIN in r13).
__device__ __forceinline__ void cvt_store8(u32 hAddr, u32 lAddr, float4 v) {
    u32 h01, h23;
    asm("cvt.rn.bf16x2.f32 %0, %1, %2;" : "=r"(h01) : "f"(v.y), "f"(v.x));
    asm("cvt.rn.bf16x2.f32 %0, %1, %2;" : "=r"(h23) : "f"(v.w), "f"(v.z));
    float hx = __uint_as_float(h01 << 16);
    float hy = __uint_as_float(h01 & 0xffff0000u);
    float hz = __uint_as_float(h23 << 16);
    float hw = __uint_as_float(h23 & 0xffff0000u);
    u32 l01, l23;
    float lx = v.x - hx, ly = v.y - hy, lz = v.z - hz, lw = v.w - hw;
    asm("cvt.rn.bf16x2.f32 %0, %1, %2;" : "=r"(l01) : "f"(ly), "f"(lx));
    asm("cvt.rn.bf16x2.f32 %0, %1, %2;" : "=r"(l23) : "f"(lw), "f"(lz));
    asm volatile("st.shared.v2.b32 [%0], {%1, %2};" :: "r"(hAddr), "r"(h01), "r"(h23) : "memory");
    asm volatile("st.shared.v2.b32 [%0], {%1, %2};" :: "r"(lAddr), "r"(l01), "r"(l23) : "memory");
}

// ============ HMMA skinny GEMM (verified): C[64, 64@n0] = A[64,4096] @ W^T ============
#define KC 32
#define RSTRIDE 40
__device__ __forceinline__ void mma_gemm(const float* __restrict__ A,
                                         const float* __restrict__ W,
                                         float* __restrict__ Cc,
                                         long cstride) {
    __shared__ __align__(16) __nv_bfloat16 tiles[4][64][RSTRIDE];
    const int tid = threadIdx.x;
    const int lane = tid & 31, wid = tid >> 5;
    const int wm = (wid & 3) << 4;
    const int wn = (wid >> 2) << 5;

    const u32 bAh = smem_u32(tiles[0]);
    const u32 bAl = smem_u32(tiles[1]);
    const u32 bWh = smem_u32(tiles[2]);
    const u32 bWl = smem_u32(tiles[3]);

    const int r0 = tid >> 3;
    const int c4 = tid & 7;
    const u32 soff0 = (u32)(r0 * (RSTRIDE * 2) + c4 * 8);
    const u32 soff1 = (u32)((r0 + 32) * (RSTRIDE * 2) + c4 * 8);

    const int lrow = (lane & 7) + ((lane >> 3) & 1) * 8;
    const int lcol = (lane >> 4) * 8;
    u32 aAddrH[2], aAddrL[2], wAddrH[2][2], wAddrL[2][2];
#pragma unroll
    for (int ks = 0; ks < 2; ks++) {
        u32 off = (u32)((wm + lrow) * (RSTRIDE * 2) + (ks * 16 + lcol) * 2);
        aAddrH[ks] = bAh + off;
        aAddrL[ks] = bAl + off;
#pragma unroll
        for (int g = 0; g < 2; g++) {
            u32 woff = (u32)((wn + g * 16 + lrow) * (RSTRIDE * 2) + (ks * 16 + lcol) * 2);
            wAddrH[ks][g] = bWh + woff;
            wAddrL[ks][g] = bWl + woff;
        }
    }

    float acc[4][4];
#pragma unroll
    for (int j = 0; j < 4; j++)
#pragma unroll
        for (int i = 0; i < 4; i++) acc[j][i] = 0.f;

    float4 aR0 = *reinterpret_cast<const float4*>(&A[(long)r0 * DIMD + c4 * 4]);
    float4 aR1 = *reinterpret_cast<const float4*>(&A[(long)(r0 + 32) * DIMD + c4 * 4]);
    float4 wR0 = *reinterpret_cast<const float4*>(&W[(long)r0 * DIMD + c4 * 4]);
    float4 wR1 = *reinterpret_cast<const float4*>(&W[(long)(r0 + 32) * DIMD + c4 * 4]);

    for (int c = 0; c < DIMD / KC; c++) {
        __syncthreads();
        cvt_store8(bAh + soff0, bAl + soff0, aR0);
        cvt_store8(bAh + soff1, bAl + soff1, aR1);
        cvt_store8(bWh + soff0, bWl + soff0, wR0);
        cvt_store8(bWh + soff1, bWl + soff1, wR1);
        __syncthreads();

        if (c + 1 < DIMD / KC) {
            const int k0 = (c + 1) * KC;
            aR0 = *reinterpret_cast<const float4*>(&A[(long)r0 * DIMD + k0 + c4 * 4]);
            aR1 = *reinterpret_cast<const float4*>(&A[(long)(r0 + 32) * DIMD + k0 + c4 * 4]);
            wR0 = *reinterpret_cast<const float4*>(&W[(long)r0 * DIMD + k0 + c4 * 4]);
            wR1 = *reinterpret_cast<const float4*>(&W[(long)(r0 + 32) * DIMD + k0 + c4 * 4]);
        }

#pragma unroll
        for (int ks = 0; ks < 2; ks++) {
            u32 ah[4], al[4];
            LDMX4(ah[0], ah[1], ah[2], ah[3], aAddrH[ks]);
            LDMX4(al[0], al[1], al[2], al[3], aAddrL[ks]);
#pragma unroll
            for (int g = 0; g < 2; g++) {
                u32 wh[4], wl[4];
                LDMX4(wh[0], wh[1], wh[2], wh[3], wAddrH[ks][g]);
                LDMX4(wl[0], wl[1], wl[2], wl[3], wAddrL[ks][g]);
#pragma unroll
                for (int j = 0; j < 2; j++) {
                    float* d = acc[2 * g + j];
                    MMA_BF16(d, ah, wh[j], wh[j + 2]);
                    MMA_BF16(d, ah, wl[j], wl[j + 2]);
                    MMA_BF16(d, al, wh[j], wh[j + 2]);
                }
            }
        }
    }

    const int er = lane >> 2, ec = (lane & 3) << 1;
#pragma unroll
    for (int j = 0; j < 4; j++) {
        int col = wn + j * 8 + ec;
        *reinterpret_cast<float2*>(&Cc[(long)(wm + er) * cstride + col]) =
            make_float2(acc[j][0], acc[j][1]);
        *reinterpret_cast<float2*>(&Cc[(long)(wm + er + 8) * cstride + col]) =
            make_float2(acc[j][2], acc[j][3]);
    }
}

__global__ __launch_bounds__(256) void gemm_qkv_mma(const float* __restrict__ x,
                                                    const float* __restrict__ wq,
                                                    const float* __restrict__ wk,
                                                    const float* __restrict__ wv) {
    int n = blockIdx.x << 6;
    int mtx = n >> 12, nw = n & 4095;
    const float* W = (mtx == 0) ? wq : ((mtx == 1) ? wk : wv);
    mma_gemm(x, W + (long)nw * DIMD, g_qkv + (long)mtx * SZQ + nw, DIMD);
}

__global__ __launch_bounds__(256) void gemm_out_mma(const float* __restrict__ wo,
                                                    float* __restrict__ outO) {
    int n0 = blockIdx.x << 6;
    mma_gemm(g_attn, wo + (long)n0 * DIMD, outO + n0, DIMD);
}

// ---------------- RoPE + scatter new K/V rows into d_out ----------------
__global__ void rope_scatter_kernel(const float* __restrict__ fc,
                                    const float* __restrict__ fs,
                                    float* __restrict__ dout) {
    int idx = blockIdx.x * 256 + threadIdx.x;
    int row = idx >> 11;
    int p   = idx & 2047;
    int h   = p >> 6;
    int i   = p & 63;
    int b = row >> 4, q = row & 15;
    int col = h * HD + 2 * i;
    float c = fc[q * 64 + i], s = fs[q * 64 + i];

    long src = (long)row * DIMD + col;
    float q0 = g_qkv[src], q1 = g_qkv[src + 1];
    g_xq[src]     = q0 * c - q1 * s;
    g_xq[src + 1] = q0 * s + q1 * c;
    float k0 = g_qkv[SZQ + src], k1 = g_qkv[SZQ + src + 1];
    long dst = (((long)(b * TTOT + CL + q)) * NHD + h) * HD + 2 * i;
    dout[dst]            = k0 * c - k1 * s;
    dout[dst + 1]        = k0 * s + k1 * c;
    dout[VOFF + dst]     = g_qkv[2 * SZQ + src];
    dout[VOFF + dst + 1] = g_qkv[2 * SZQ + src + 1];
}

// ============ HMMA split-KV flash attention + fused cache copy ============
// grid 2048 = (b,h,split), 256 threads = 8 warps, NATURAL occupancy (no cap).
// Register prefetch double-buffer: tile t+1's K/V LDGs issued before tile t's
// MMA/softmax work, consumed after ~2-3K cyc of compute (hides DRAM latency).
__global__ __launch_bounds__(256) void attn_kernel(const float* __restrict__ kc,
                                                   const float* __restrict__ vc,
                                                   const float* __restrict__ mask,
                                                   float* __restrict__ dout) {
    const int blk = blockIdx.x;
    const int bh = blk >> 4, s = blk & 15;
    const int b = bh >> 5, h = bh & 31;
    const int tstart = s * RANGE;
    const int tend   = tstart + RANGE;

    __shared__ __align__(16) __nv_bfloat16 Khi[TT][136], Klo[TT][136];
    __shared__ __align__(16) __nv_bfloat16 Vhi[TT][136], Vlo[TT][136];
    __shared__ __align__(16) __nv_bfloat16 Qhi[16][136], Qlo[16][136];
    __shared__ __align__(16) __nv_bfloat16 Phi[16][40], Plo[16][40];
    __shared__ float Ps[16][34];
    __shared__ float m_sh[16], l_sh[16], corr_sh[16];

    const int tid = threadIdx.x;
    const int lane = tid & 31, wid = tid >> 5;
    const int rq = tid >> 4, rc = tid & 15;

    const u32 bKh = smem_u32(Khi), bKl = smem_u32(Klo);
    const u32 bVh = smem_u32(Vhi), bVl = smem_u32(Vlo);
    const u32 bQh = smem_u32(Qhi), bQl = smem_u32(Qlo);
    const u32 bPh = smem_u32(Phi), bPl = smem_u32(Plo);

    // load roped Q (16x128), convert to hi/lo bf16
#pragma unroll
    for (int i = 0; i < 2; i++) {
        int idx = tid + i * 256;
        int q = idx >> 5, c4 = idx & 31;
        float4 v = *reinterpret_cast<const float4*>(&g_xq[(long)(b * 16 + q) * DIMD + h * HD + c4 * 4]);
        u32 off = (u32)(q * 272 + c4 * 8);
        cvt_store8(bQh + off, bQl + off, v);
    }
    if (tid < 16) { m_sh[tid] = -1e30f; l_sh[tid] = 0.0f; }

    const int lrow = (lane & 7) + ((lane >> 3) & 1) * 8;
    const int lc8  = (lane >> 4) * 8;
    const u32 qBase = (u32)(lrow * 272 + lc8 * 2);
    const u32 kBase = (u32)((8 * (wid & 3) + (lane & 7)) * 272 + ((lane >> 3) & 1) * 16);
    const u32 pBase = (u32)(lrow * 80 + lc8 * 2);
    const int wd = wid * 16;
    const u32 vBase = (u32)(((lane & 7) + ((lane >> 4) & 1) * 8) * 272 +
                            (wd + ((lane >> 3) & 1) * 8) * 2);

    float oacc[2][4];
#pragma unroll
    for (int g = 0; g < 2; g++)
#pragma unroll
        for (int i = 0; i < 4; i++) oacc[g][i] = 0.f;

    float* knew = dout;
    float* vnew = dout + VOFF;

    // ---- prefetch tile 0 into registers ----
    float4 kvR[4], vvR[4];
    {
        const int rows0 = min(TT, tend - tstart);
#pragma unroll
        for (int i = 0; i < 4; i++) {
            int idx = tid + i * 256;
            int r = idx >> 5, c4 = idx & 31;
            int t = tstart + r;
            if (r < rows0) {
                if (t < CL) {
                    long src = (((long)(b * CL + t)) * NHD + h) * HD + c4 * 4;
                    kvR[i] = *reinterpret_cast<const float4*>(&kc[src]);
                    vvR[i] = *reinterpret_cast<const float4*>(&vc[src]);
                } else {
                    long dst = (((long)(b * TTOT + t)) * NHD + h) * HD + c4 * 4;
                    kvR[i] = *reinterpret_cast<const float4*>(&knew[dst]);
                    vvR[i] = *reinterpret_cast<const float4*>(&vnew[dst]);
                }
            }
        }
    }

    for (int t0 = tstart; t0 < tend; t0 += TT) {
        const int rows = min(TT, tend - t0);
        __syncthreads();   // prev-tile frag reads done

        // ---- drain regs: gmem cache copy + cvt to bf16 hi/lo smem ----
#pragma unroll
        for (int i = 0; i < 4; i++) {
            int idx = tid + i * 256;
            int r = idx >> 5, c4 = idx & 31;
            int t = t0 + r;
            if (r < rows) {
                if (t < CL) {
                    long dst = (((long)(b * TTOT + t)) * NHD + h) * HD + c4 * 4;
                    *reinterpret_cast<float4*>(&knew[dst]) = kvR[i];
                    *reinterpret_cast<float4*>(&vnew[dst]) = vvR[i];
                }
                u32 off = (u32)(r * 272 + c4 * 8);
                cvt_store8(bKh + off, bKl + off, kvR[i]);
                cvt_store8(bVh + off, bVl + off, vvR[i]);
            }
        }
        __syncthreads();

        // ---- prefetch next tile (overlaps MMA/softmax below) ----
        if (t0 + TT < tend) {
            const int rowsn = min(TT, tend - (t0 + TT));
#pragma unroll
            for (int i = 0; i < 4; i++) {
                int idx = tid + i * 256;
                int r = idx >> 5, c4 = idx & 31;
                int t = t0 + TT + r;
                if (r < rowsn) {
                    if (t < CL) {
                        long src = (((long)(b * CL + t)) * NHD + h) * HD + c4 * 4;
                        kvR[i] = *reinterpret_cast<const float4*>(&kc[src]);
                        vvR[i] = *reinterpret_cast<const float4*>(&vc[src]);
                    } else {
                        long dst = (((long)(b * TTOT + t)) * NHD + h) * HD + c4 * 4;
                        kvR[i] = *reinterpret_cast<const float4*>(&knew[dst]);
                        vvR[i] = *reinterpret_cast<const float4*>(&vnew[dst]);
                    }
                }
            }
        }

        // ---- S = Q@K^T via HMMA (warps 0-3, t8 slice each) ----
        if (wid < 4) {
            float sa[4] = {0.f, 0.f, 0.f, 0.f};
#pragma unroll
            for (int ks = 0; ks < 8; ks++) {
                u32 qo = (u32)(ks * 32);
                u32 qh[4], ql[4], kh0, kh1, kl0, kl1;
                LDMX4(qh[0], qh[1], qh[2], qh[3], bQh + qBase + qo);
                LDMX4(ql[0], ql[1], ql[2], ql[3], bQl + qBase + qo);
                LDMX2(kh0, kh1, bKh + kBase + qo);
                LDMX2(kl0, kl1, bKl + kBase + qo);
                MMA_BF16(sa, qh, kh0, kh1);
                MMA_BF16(sa, qh, kl0, kl1);
                MMA_BF16(sa, ql, kh0, kh1);
            }
            int er = lane >> 2, ec = (lane & 3) << 1;
            *reinterpret_cast<float2*>(&Ps[er][8 * wid + ec])     = make_float2(sa[0], sa[1]);
            *reinterpret_cast<float2*>(&Ps[er + 8][8 * wid + ec]) = make_float2(sa[2], sa[3]);
        }
        __syncthreads();

        // ---- online softmax + P hi/lo conversion (all 256 threads) ----
        {
            float mprev = m_sh[rq];
            float v0 = (rc < rows)      ? Ps[rq][rc] * INV_SQRT_HD      + mask[rq * TTOT + t0 + rc]      : -1e30f;
            float v1 = (rc + 16 < rows) ? Ps[rq][rc + 16] * INV_SQRT_HD + mask[rq * TTOT + t0 + rc + 16] : -1e30f;
            float mx = fmaxf(v0, v1);
#pragma unroll
            for (int m = 8; m; m >>= 1) mx = fmaxf(mx, __shfl_xor_sync(0xffffffffu, mx, m));
            float tm = fmaxf(mprev, mx);
            float p0 = __expf(v0 - tm), p1 = __expf(v1 - tm);
            __nv_bfloat16 h0 = __float2bfloat16(p0);
            __nv_bfloat16 h1 = __float2bfloat16(p1);
            Phi[rq][rc]      = h0;
            Phi[rq][rc + 16] = h1;
            Plo[rq][rc]      = __float2bfloat16(p0 - __bfloat162float(h0));
            Plo[rq][rc + 16] = __float2bfloat16(p1 - __bfloat162float(h1));
            float sum = p0 + p1;
#pragma unroll
            for (int m = 8; m; m >>= 1) sum += __shfl_xor_sync(0xffffffffu, sum, m);
            if (rc == 0) {
                float corr = __expf(mprev - tm);
                corr_sh[rq] = corr;
                m_sh[rq] = tm;
                l_sh[rq] = l_sh[rq] * corr + sum;
            }
        }
        __syncthreads();

        // ---- O = corr*O + P@V via HMMA (8 warps, d16 slice each) ----
        {
            int er = lane >> 2;
            float c0 = corr_sh[er], c1 = corr_sh[er + 8];
#pragma unroll
            for (int g = 0; g < 2; g++) {
                oacc[g][0] *= c0; oacc[g][1] *= c0;
                oacc[g][2] *= c1; oacc[g][3] *= c1;
            }
#pragma unroll
            for (int kcs = 0; kcs < 2; kcs++) {
                u32 po = (u32)(kcs * 32);
                u32 vo = (u32)(kcs * 16 * 272);
                u32 ph[4], pl[4], vh[4], vl[4];
                LDMX4(ph[0], ph[1], ph[2], ph[3], bPh + pBase + po);
                LDMX4(pl[0], pl[1], pl[2], pl[3], bPl + pBase + po);
                LDMX4T(vh[0], vh[1], vh[2], vh[3], bVh + vBase + vo);
                LDMX4T(vl[0], vl[1], vl[2], vl[3], bVl + vBase + vo);
#pragma unroll
                for (int g = 0; g < 2; g++) {
                    MMA_BF16(oacc[g], ph, vh[g], vh[g + 2]);
                    MMA_BF16(oacc[g], ph, vl[g], vl[g + 2]);
                    MMA_BF16(oacc[g], pl, vh[g], vh[g + 2]);
                }
            }
        }
    }

    // ---- epilogue: write UNNORMALIZED partial O + m,l (combine normalizes) ----
    {
        int er = lane >> 2, ec = (lane & 3) << 1;
        long base = (long)(bh * NS + s) * 16;
#pragma unroll
        for (int g = 0; g < 2; g++) {
            *reinterpret_cast<float2*>(&g_ao[(base + er) * HD + wd + g * 8 + ec]) =
                make_float2(oacc[g][0], oacc[g][1]);
            *reinterpret_cast<float2*>(&g_ao[(base + er + 8) * HD + wd + g * 8 + ec]) =
                make_float2(oacc[g][2], oacc[g][3]);
        }
        if (tid < 16) {
            g_am[(bh * NS + s) * 16 + tid] = m_sh[tid];
            g_al[(bh * NS + s) * 16 + tid] = l_sh[tid];
        }
    }
}

// ---------------- combine split-KV partials (512 CTAs: bh x d-quarter) ----------------
__global__ void attn_combine_kernel() {
    const int bid = blockIdx.x;           // 0..511
    const int bh = bid >> 2, qd = bid & 3;
    const int b = bh >> 5, h = bh & 31;
    const int tid = threadIdx.x;
    __shared__ float w_sh[16][NS];
    __shared__ float linv_sh[16];

    if (tid < 16) {
        float mm[NS];
        float M = -1e30f;
#pragma unroll
        for (int s = 0; s < NS; s++) {
            mm[s] = g_am[(bh * NS + s) * 16 + tid];
            M = fmaxf(M, mm[s]);
        }
        float L = 0.f;
#pragma unroll
        for (int s = 0; s < NS; s++) {
            float w = __expf(mm[s] - M);
            w_sh[tid][s] = w;
            L += w * g_al[(bh * NS + s) * 16 + tid];
        }
        linv_sh[tid] = 1.0f / L;
    }
    __syncthreads();

    const int q = tid >> 4, d0 = qd * 32 + (tid & 15) * 2;
    float acc0 = 0.f, acc1 = 0.f;
#pragma unroll
    for (int s = 0; s < NS; s++) {
        float w = w_sh[q][s];
        const float* P = &g_ao[((long)(bh * NS + s) * 16 + q) * HD + d0];
        acc0 += w * P[0];
        acc1 += w * P[1];
    }
    float linv = linv_sh[q];
    long ob = (long)(b * 16 + q) * DIMD + h * HD + d0;
    g_attn[ob]     = acc0 * linv;
    g_attn[ob + 1] = acc1 * linv;
}

// ---------------- launch ----------------
extern "C" void kernel_launch(void* const* d_in, const int* in_sizes, int n_in,
                              void* d_out, int out_size) {
    const float* x    = (const float*)d_in[0];
    const float* kc   = (const float*)d_in[1];
    const float* vc   = (const float*)d_in[2];
    const float* fc   = (const float*)d_in[3];
    const float* fs   = (const float*)d_in[4];
    const float* mask = (const float*)d_in[5];
    const float* wq   = (const float*)d_in[6];
    const float* wk   = (const float*)d_in[7];
    const float* wv   = (const float*)d_in[8];
    const float* wo   = (const float*)d_in[9];
    float* out = (float*)d_out;

    gemm_qkv_mma<<<192, 256>>>(x, wq, wk, wv);
    rope_scatter_kernel<<<512, 256>>>(fc, fs, out);
    attn_kernel<<<BSB * NHD * NS, 256>>>(kc, vc, mask, out);
    attn_combine_kernel<<<512, 256>>>();
    gemm_out_mma<<<64, 256>>>(wo, out + OOFF);
}

// round 16
// speedup vs baseline: 1.1552x; 1.1552x over previous
#include <cuda_runtime.h>
#include <cuda_bf16.h>
#include <math.h>
#include <stdint.h>

typedef unsigned long long u64;
typedef unsigned int u32;

// ---------------- problem constants ----------------
#define NHD   32
#define HD    128
#define BSB   4
#define QL    16
#define CL    4096
#define TTOT  (CL + QL)        // 4112
#define DIMD  4096
#define MROWS 64
#define SZQ   (MROWS * DIMD)   // 262144
#define NS    16               // attention kv splits
#define RANGE 257
#define TT    32               // attention time tile

#define VOFF  ((long)BSB * TTOT * NHD * HD)
#define OOFF  (2l * VOFF)
#define INV_SQRT_HD 0.08838834764831845f

// ---------------- scratch ----------------
__device__ float g_qkv[3l * SZQ];     // xq|xk|xv projections (fp32)
__device__ float g_xq [SZQ];          // roped Q
__device__ float g_attn[SZQ];         // attention out (pre out-proj)
__device__ float g_ao  [(long)BSB * NHD * NS * QL * HD];
__device__ float g_am  [BSB * NHD * NS * QL];
__device__ float g_al  [BSB * NHD * NS * QL];

// ---------------- helpers ----------------
__device__ __forceinline__ u32 smem_u32(const void* p) {
    u32 a;
    asm("{ .reg .u64 t; cvta.to.shared.u64 t, %1; cvt.u32.u64 %0, t; }" : "=r"(a) : "l"(p));
    return a;
}

#define LDMX4(r0, r1, r2, r3, addr) \
    asm volatile("ldmatrix.sync.aligned.m8n8.x4.shared.b16 {%0,%1,%2,%3}, [%4];" \
                 : "=r"(r0), "=r"(r1), "=r"(r2), "=r"(r3) : "r"(addr))

#define LDMX4T(r0, r1, r2, r3, addr) \
    asm volatile("ldmatrix.sync.aligned.m8n8.x4.trans.shared.b16 {%0,%1,%2,%3}, [%4];" \
                 : "=r"(r0), "=r"(r1), "=r"(r2), "=r"(r3) : "r"(addr))

#define LDMX2(r0, r1, addr) \
    asm volatile("ldmatrix.sync.aligned.m8n8.x2.shared.b16 {%0,%1}, [%2];" \
                 : "=r"(r0), "=r"(r1) : "r"(addr))

#define MMA_BF16(d, a, b0, b1) \
    asm volatile("mma.sync.aligned.m16n8k16.row.col.f32.bf16.bf16.f32 " \
                 "{%0,%1,%2,%3}, {%4,%5,%6,%7}, {%8,%9}, {%0,%1,%2,%3};" \
                 : "+f"((d)[0]), "+f"((d)[1]), "+f"((d)[2]), "+f"((d)[3]) \
                 : "r"((a)[0]), "r"((a)[1]), "r"((a)[2]), "r"((a)[3]), "r"(b0), "r"(b1))

// convert float4 -> bf16 hi pair + lo pair, store 8B each.
// hi floats reconstructed from packed bf16 bits (SHL/AND): identical values,
// half the cvt-pipe ops (measured WIN in r13).
__device__ __forceinline__ void cvt_store8(u32 hAddr, u32 lAddr, float4 v) {
    u32 h01, h23;
    asm("cvt.rn.bf16x2.f32 %0, %1, %2;" : "=r"(h01) : "f"(v.y), "f"(v.x));
    asm("cvt.rn.bf16x2.f32 %0, %1, %2;" : "=r"(h23) : "f"(v.w), "f"(v.z));
    float hx = __uint_as_float(h01 << 16);
    float hy = __uint_as_float(h01 & 0xffff0000u);
    float hz = __uint_as_float(h23 << 16);
    float hw = __uint_as_float(h23 & 0xffff0000u);
    u32 l01, l23;
    float lx = v.x - hx, ly = v.y - hy, lz = v.z - hz, lw = v.w - hw;
    asm("cvt.rn.bf16x2.f32 %0, %1, %2;" : "=r"(l01) : "f"(ly), "f"(lx));
    asm("cvt.rn.bf16x2.f32 %0, %1, %2;" : "=r"(l23) : "f"(lw), "f"(lz));
    asm volatile("st.shared.v2.b32 [%0], {%1, %2};" :: "r"(hAddr), "r"(h01), "r"(h23) : "memory");
    asm volatile("st.shared.v2.b32 [%0], {%1, %2};" :: "r"(lAddr), "r"(l01), "r"(l23) : "memory");
}

// ============ HMMA skinny GEMM (verified): C[64, 64@n0] = A[64,4096] @ W^T ============
#define KC 32
#define RSTRIDE 40
__device__ __forceinline__ void mma_gemm(const float* __restrict__ A,
                                         const float* __restrict__ W,
                                         float* __restrict__ Cc,
                                         long cstride) {
    __shared__ __align__(16) __nv_bfloat16 tiles[4][64][RSTRIDE];
    const int tid = threadIdx.x;
    const int lane = tid & 31, wid = tid >> 5;
    const int wm = (wid & 3) << 4;
    const int wn = (wid >> 2) << 5;

    const u32 bAh = smem_u32(tiles[0]);
    const u32 bAl = smem_u32(tiles[1]);
    const u32 bWh = smem_u32(tiles[2]);
    const u32 bWl = smem_u32(tiles[3]);

    const int r0 = tid >> 3;
    const int c4 = tid & 7;
    const u32 soff0 = (u32)(r0 * (RSTRIDE * 2) + c4 * 8);
    const u32 soff1 = (u32)((r0 + 32) * (RSTRIDE * 2) + c4 * 8);

    const int lrow = (lane & 7) + ((lane >> 3) & 1) * 8;
    const int lcol = (lane >> 4) * 8;
    u32 aAddrH[2], aAddrL[2], wAddrH[2][2], wAddrL[2][2];
#pragma unroll
    for (int ks = 0; ks < 2; ks++) {
        u32 off = (u32)((wm + lrow) * (RSTRIDE * 2) + (ks * 16 + lcol) * 2);
        aAddrH[ks] = bAh + off;
        aAddrL[ks] = bAl + off;
#pragma unroll
        for (int g = 0; g < 2; g++) {
            u32 woff = (u32)((wn + g * 16 + lrow) * (RSTRIDE * 2) + (ks * 16 + lcol) * 2);
            wAddrH[ks][g] = bWh + woff;
            wAddrL[ks][g] = bWl + woff;
        }
    }

    float acc[4][4];
#pragma unroll
    for (int j = 0; j < 4; j++)
#pragma unroll
        for (int i = 0; i < 4; i++) acc[j][i] = 0.f;

    float4 aR0 = *reinterpret_cast<const float4*>(&A[(long)r0 * DIMD + c4 * 4]);
    float4 aR1 = *reinterpret_cast<const float4*>(&A[(long)(r0 + 32) * DIMD + c4 * 4]);
    float4 wR0 = *reinterpret_cast<const float4*>(&W[(long)r0 * DIMD + c4 * 4]);
    float4 wR1 = *reinterpret_cast<const float4*>(&W[(long)(r0 + 32) * DIMD + c4 * 4]);

    for (int c = 0; c < DIMD / KC; c++) {
        __syncthreads();
        cvt_store8(bAh + soff0, bAl + soff0, aR0);
        cvt_store8(bAh + soff1, bAl + soff1, aR1);
        cvt_store8(bWh + soff0, bWl + soff0, wR0);
        cvt_store8(bWh + soff1, bWl + soff1, wR1);
        __syncthreads();

        if (c + 1 < DIMD / KC) {
            const int k0 = (c + 1) * KC;
            aR0 = *reinterpret_cast<const float4*>(&A[(long)r0 * DIMD + k0 + c4 * 4]);
            aR1 = *reinterpret_cast<const float4*>(&A[(long)(r0 + 32) * DIMD + k0 + c4 * 4]);
            wR0 = *reinterpret_cast<const float4*>(&W[(long)r0 * DIMD + k0 + c4 * 4]);
            wR1 = *reinterpret_cast<const float4*>(&W[(long)(r0 + 32) * DIMD + k0 + c4 * 4]);
        }

#pragma unroll
        for (int ks = 0; ks < 2; ks++) {
            u32 ah[4], al[4];
            LDMX4(ah[0], ah[1], ah[2], ah[3], aAddrH[ks]);
            LDMX4(al[0], al[1], al[2], al[3], aAddrL[ks]);
#pragma unroll
            for (int g = 0; g < 2; g++) {
                u32 wh[4], wl[4];
                LDMX4(wh[0], wh[1], wh[2], wh[3], wAddrH[ks][g]);
                LDMX4(wl[0], wl[1], wl[2], wl[3], wAddrL[ks][g]);
#pragma unroll
                for (int j = 0; j < 2; j++) {
                    float* d = acc[2 * g + j];
                    MMA_BF16(d, ah, wh[j], wh[j + 2]);
                    MMA_BF16(d, ah, wl[j], wl[j + 2]);
                    MMA_BF16(d, al, wh[j], wh[j + 2]);
                }
            }
        }
    }

    const int er = lane >> 2, ec = (lane & 3) << 1;
#pragma unroll
    for (int j = 0; j < 4; j++) {
        int col = wn + j * 8 + ec;
        *reinterpret_cast<float2*>(&Cc[(long)(wm + er) * cstride + col]) =
            make_float2(acc[j][0], acc[j][1]);
        *reinterpret_cast<float2*>(&Cc[(long)(wm + er + 8) * cstride + col]) =
            make_float2(acc[j][2], acc[j][3]);
    }
}

__global__ __launch_bounds__(256) void gemm_qkv_mma(const float* __restrict__ x,
                                                    const float* __restrict__ wq,
                                                    const float* __restrict__ wk,
                                                    const float* __restrict__ wv) {
    int n = blockIdx.x << 6;
    int mtx = n >> 12, nw = n & 4095;
    const float* W = (mtx == 0) ? wq : ((mtx == 1) ? wk : wv);
    mma_gemm(x, W + (long)nw * DIMD, g_qkv + (long)mtx * SZQ + nw, DIMD);
}

__global__ __launch_bounds__(256) void gemm_out_mma(const float* __restrict__ wo,
                                                    float* __restrict__ outO) {
    int n0 = blockIdx.x << 6;
    mma_gemm(g_attn, wo + (long)n0 * DIMD, outO + n0, DIMD);
}

// ---------------- RoPE + scatter new K/V rows into d_out ----------------
__global__ void rope_scatter_kernel(const float* __restrict__ fc,
                                    const float* __restrict__ fs,
                                    float* __restrict__ dout) {
    int idx = blockIdx.x * 256 + threadIdx.x;
    int row = idx >> 11;
    int p   = idx & 2047;
    int h   = p >> 6;
    int i   = p & 63;
    int b = row >> 4, q = row & 15;
    int col = h * HD + 2 * i;
    float c = fc[q * 64 + i], s = fs[q * 64 + i];

    long src = (long)row * DIMD + col;
    float q0 = g_qkv[src], q1 = g_qkv[src + 1];
    g_xq[src]     = q0 * c - q1 * s;
    g_xq[src + 1] = q0 * s + q1 * c;
    float k0 = g_qkv[SZQ + src], k1 = g_qkv[SZQ + src + 1];
    long dst = (((long)(b * TTOT + CL + q)) * NHD + h) * HD + 2 * i;
    dout[dst]            = k0 * c - k1 * s;
    dout[dst + 1]        = k0 * s + k1 * c;
    dout[VOFF + dst]     = g_qkv[2 * SZQ + src];
    dout[VOFF + dst + 1] = g_qkv[2 * SZQ + src + 1];
}

// ============ HMMA split-KV flash attention + fused cache copy (r13 body) ============
// grid 2048 with s OUTERMOST: blk = s*128 + (b*32+h). Concurrently-resident CTAs
// are consecutive heads on the SAME t-range -> contiguous DRAM sweeps instead of
// scattered 512B chunks at 16KB stride.
__global__ __launch_bounds__(256) void attn_kernel(const float* __restrict__ kc,
                                                   const float* __restrict__ vc,
                                                   const float* __restrict__ mask,
                                                   float* __restrict__ dout) {
    const int blk = blockIdx.x;
    const int s = blk >> 7, bh = blk & 127;       // s outermost (locality remap)
    const int b = bh >> 5, h = bh & 31;
    const int tstart = s * RANGE;
    const int tend   = tstart + RANGE;

    __shared__ __align__(16) __nv_bfloat16 Khi[TT][136], Klo[TT][136];
    __shared__ __align__(16) __nv_bfloat16 Vhi[TT][136], Vlo[TT][136];
    __shared__ __align__(16) __nv_bfloat16 Qhi[16][136], Qlo[16][136];
    __shared__ __align__(16) __nv_bfloat16 Phi[16][40], Plo[16][40];
    __shared__ float Ps[16][34];
    __shared__ float m_sh[16], l_sh[16], corr_sh[16];

    const int tid = threadIdx.x;
    const int lane = tid & 31, wid = tid >> 5;
    const int rq = tid >> 4, rc = tid & 15;

    const u32 bKh = smem_u32(Khi), bKl = smem_u32(Klo);
    const u32 bVh = smem_u32(Vhi), bVl = smem_u32(Vlo);
    const u32 bQh = smem_u32(Qhi), bQl = smem_u32(Qlo);
    const u32 bPh = smem_u32(Phi), bPl = smem_u32(Plo);

    // load roped Q (16x128), convert to hi/lo bf16
#pragma unroll
    for (int i = 0; i < 2; i++) {
        int idx = tid + i * 256;
        int q = idx >> 5, c4 = idx & 31;
        float4 v = *reinterpret_cast<const float4*>(&g_xq[(long)(b * 16 + q) * DIMD + h * HD + c4 * 4]);
        u32 off = (u32)(q * 272 + c4 * 8);
        cvt_store8(bQh + off, bQl + off, v);
    }
    if (tid < 16) { m_sh[tid] = -1e30f; l_sh[tid] = 0.0f; }

    const int lrow = (lane & 7) + ((lane >> 3) & 1) * 8;
    const int lc8  = (lane >> 4) * 8;
    const u32 qBase = (u32)(lrow * 272 + lc8 * 2);
    const u32 kBase = (u32)((8 * (wid & 3) + (lane & 7)) * 272 + ((lane >> 3) & 1) * 16);
    const u32 pBase = (u32)(lrow * 80 + lc8 * 2);
    const int wd = wid * 16;
    const u32 vBase = (u32)(((lane & 7) + ((lane >> 4) & 1) * 8) * 272 +
                            (wd + ((lane >> 3) & 1) * 8) * 2);

    float oacc[2][4];
#pragma unroll
    for (int g = 0; g < 2; g++)
#pragma unroll
        for (int i = 0; i < 4; i++) oacc[g][i] = 0.f;

    float* knew = dout;
    float* vnew = dout + VOFF;

    for (int t0 = tstart; t0 < tend; t0 += TT) {
        const int rows = min(TT, tend - t0);
        __syncthreads();   // prev-tile frag reads done (and Q tile ready on iter 0)

        // ---- load K/V fp32, fused cache copy, convert to bf16 hi/lo smem ----
#pragma unroll
        for (int i = 0; i < 4; i++) {
            int idx = tid + i * 256;
            int r = idx >> 5, c4 = idx & 31;
            int t = t0 + r;
            if (r < rows) {
                long dst = (((long)(b * TTOT + t)) * NHD + h) * HD + c4 * 4;
                float4 kv, vv;
                if (t < CL) {
                    long src = (((long)(b * CL + t)) * NHD + h) * HD + c4 * 4;
                    kv = *reinterpret_cast<const float4*>(&kc[src]);
                    vv = *reinterpret_cast<const float4*>(&vc[src]);
                    *reinterpret_cast<float4*>(&knew[dst]) = kv;
                    *reinterpret_cast<float4*>(&vnew[dst]) = vv;
                } else {
                    kv = *reinterpret_cast<const float4*>(&knew[dst]);
                    vv = *reinterpret_cast<const float4*>(&vnew[dst]);
                }
                u32 off = (u32)(r * 272 + c4 * 8);
                cvt_store8(bKh + off, bKl + off, kv);
                cvt_store8(bVh + off, bVl + off, vv);
            }
        }
        __syncthreads();

        // ---- S = Q@K^T via HMMA (warps 0-3, t8 slice each) ----
        if (wid < 4) {
            float sa[4] = {0.f, 0.f, 0.f, 0.f};
#pragma unroll
            for (int ks = 0; ks < 8; ks++) {
                u32 qo = (u32)(ks * 32);
                u32 qh[4], ql[4], kh0, kh1, kl0, kl1;
                LDMX4(qh[0], qh[1], qh[2], qh[3], bQh + qBase + qo);
                LDMX4(ql[0], ql[1], ql[2], ql[3], bQl + qBase + qo);
                LDMX2(kh0, kh1, bKh + kBase + qo);
                LDMX2(kl0, kl1, bKl + kBase + qo);
                MMA_BF16(sa, qh, kh0, kh1);
                MMA_BF16(sa, qh, kl0, kl1);
                MMA_BF16(sa, ql, kh0, kh1);
            }
            int er = lane >> 2, ec = (lane & 3) << 1;
            *reinterpret_cast<float2*>(&Ps[er][8 * wid + ec])     = make_float2(sa[0], sa[1]);
            *reinterpret_cast<float2*>(&Ps[er + 8][8 * wid + ec]) = make_float2(sa[2], sa[3]);
        }
        __syncthreads();

        // ---- online softmax + P hi/lo conversion (all 256 threads) ----
        {
            float mprev = m_sh[rq];
            float v0 = (rc < rows)      ? Ps[rq][rc] * INV_SQRT_HD      + mask[rq * TTOT + t0 + rc]      : -1e30f;
            float v1 = (rc + 16 < rows) ? Ps[rq][rc + 16] * INV_SQRT_HD + mask[rq * TTOT + t0 + rc + 16] : -1e30f;
            float mx = fmaxf(v0, v1);
#pragma unroll
            for (int m = 8; m; m >>= 1) mx = fmaxf(mx, __shfl_xor_sync(0xffffffffu, mx, m));
            float tm = fmaxf(mprev, mx);
            float p0 = __expf(v0 - tm), p1 = __expf(v1 - tm);
            __nv_bfloat16 h0 = __float2bfloat16(p0);
            __nv_bfloat16 h1 = __float2bfloat16(p1);
            Phi[rq][rc]      = h0;
            Phi[rq][rc + 16] = h1;
            Plo[rq][rc]      = __float2bfloat16(p0 - __bfloat162float(h0));
            Plo[rq][rc + 16] = __float2bfloat16(p1 - __bfloat162float(h1));
            float sum = p0 + p1;
#pragma unroll
            for (int m = 8; m; m >>= 1) sum += __shfl_xor_sync(0xffffffffu, sum, m);
            if (rc == 0) {
                float corr = __expf(mprev - tm);
                corr_sh[rq] = corr;
                m_sh[rq] = tm;
                l_sh[rq] = l_sh[rq] * corr + sum;
            }
        }
        __syncthreads();

        // ---- O = corr*O + P@V via HMMA (8 warps, d16 slice each) ----
        {
            int er = lane >> 2;
            float c0 = corr_sh[er], c1 = corr_sh[er + 8];
#pragma unroll
            for (int g = 0; g < 2; g++) {
                oacc[g][0] *= c0; oacc[g][1] *= c0;
                oacc[g][2] *= c1; oacc[g][3] *= c1;
            }
#pragma unroll
            for (int kcs = 0; kcs < 2; kcs++) {
                u32 po = (u32)(kcs * 32);
                u32 vo = (u32)(kcs * 16 * 272);
                u32 ph[4], pl[4], vh[4], vl[4];
                LDMX4(ph[0], ph[1], ph[2], ph[3], bPh + pBase + po);
                LDMX4(pl[0], pl[1], pl[2], pl[3], bPl + pBase + po);
                LDMX4T(vh[0], vh[1], vh[2], vh[3], bVh + vBase + vo);
                LDMX4T(vl[0], vl[1], vl[2], vl[3], bVl + vBase + vo);
#pragma unroll
                for (int g = 0; g < 2; g++) {
                    MMA_BF16(oacc[g], ph, vh[g], vh[g + 2]);
                    MMA_BF16(oacc[g], ph, vl[g], vl[g + 2]);
                    MMA_BF16(oacc[g], pl, vh[g], vh[g + 2]);
                }
            }
        }
    }

    // ---- epilogue: write UNNORMALIZED partial O + m,l (combine normalizes) ----
    {
        int er = lane >> 2, ec = (lane & 3) << 1;
        long base = (long)(bh * NS + s) * 16;
#pragma unroll
        for (int g = 0; g < 2; g++) {
            *reinterpret_cast<float2*>(&g_ao[(base + er) * HD + wd + g * 8 + ec]) =
                make_float2(oacc[g][0], oacc[g][1]);
            *reinterpret_cast<float2*>(&g_ao[(base + er + 8) * HD + wd + g * 8 + ec]) =
                make_float2(oacc[g][2], oacc[g][3]);
        }
        if (tid < 16) {
            g_am[(bh * NS + s) * 16 + tid] = m_sh[tid];
            g_al[(bh * NS + s) * 16 + tid] = l_sh[tid];
        }
    }
}

// ---------------- combine split-KV partials (512 CTAs: bh x d-quarter) ----------------
__global__ void attn_combine_kernel() {
    const int bid = blockIdx.x;           // 0..511
    const int bh = bid >> 2, qd = bid & 3;
    const int b = bh >> 5, h = bh & 31;
    const int tid = threadIdx.x;
    __shared__ float w_sh[16][NS];
    __shared__ float linv_sh[16];

    if (tid < 16) {
        float mm[NS];
        float M = -1e30f;
#pragma unroll
        for (int s = 0; s < NS; s++) {
            mm[s] = g_am[(bh * NS + s) * 16 + tid];
            M = fmaxf(M, mm[s]);
        }
        float L = 0.f;
#pragma unroll
        for (int s = 0; s < NS; s++) {
            float w = __expf(mm[s] - M);
            w_sh[tid][s] = w;
            L += w * g_al[(bh * NS + s) * 16 + tid];
        }
        linv_sh[tid] = 1.0f / L;
    }
    __syncthreads();

    const int q = tid >> 4, d0 = qd * 32 + (tid & 15) * 2;
    float acc0 = 0.f, acc1 = 0.f;
#pragma unroll
    for (int s = 0; s < NS; s++) {
        float w = w_sh[q][s];
        const float* P = &g_ao[((long)(bh * NS + s) * 16 + q) * HD + d0];
        acc0 += w * P[0];
        acc1 += w * P[1];
    }
    float linv = linv_sh[q];
    long ob = (long)(b * 16 + q) * DIMD + h * HD + d0;
    g_attn[ob]     = acc0 * linv;
    g_attn[ob + 1] = acc1 * linv;
}

// ---------------- launch ----------------
extern "C" void kernel_launch(void* const* d_in, const int* in_sizes, int n_in,
                              void* d_out, int out_size) {
    const float* x    = (const float*)d_in[0];
    const float* kc   = (const float*)d_in[1];
    const float* vc   = (const float*)d_in[2];
    const float* fc   = (const float*)d_in[3];
    const float* fs   = (const float*)d_in[4];
    const float* mask = (const float*)d_in[5];
    const float* wq   = (const float*)d_in[6];
    const float* wk   = (const float*)d_in[7];
    const float* wv   = (const float*)d_in[8];
    const float* wo   = (const float*)d_in[9];
    float* out = (float*)d_out;

    gemm_qkv_mma<<<192, 256>>>(x, wq, wk, wv);
    rope_scatter_kernel<<<512, 256>>>(fc, fs, out);
    attn_kernel<<<BSB * NHD * NS, 256>>>(kc, vc, mask, out);
    attn_combine_kernel<<<512, 256>>>();
    gemm_out_mma<<<64, 256>>>(wo, out + OOFF);
}